// round 14
// baseline (speedup 1.0000x reference)
#include <cuda_runtime.h>
#include <cuda_fp16.h>
#include <cstddef>
#include <cstdint>

#define NN0 50000
#define NN1 20000
#define NN2 8000
#define NN3 3200
#define NN4 1300

// ---------------- device scratch (no allocation allowed) ----------------
__device__ float g_x0[NN0 * 32];
__device__ float g_x1[NN1 * 32];
__device__ float g_x2[NN2 * 64];
__device__ float g_x3[NN3 * 128];
__device__ float g_x4[NN4 * 256];
__device__ float g_y [NN0 * 128];
__device__ float g_ta[NN0 * 128];
__device__ float g_tb[NN0 * 128];
__device__ float g_split[4 * 1024 * 1024];
__device__ float g_p1[800 * 512];
__device__ float g_p2[800 * 512];
__device__ float g_mean[2 * 512];
__device__ float g_istd[2 * 512];

// ---------------- fp16 hi/lo helpers --------------------------------------
// x = h + l with h = fp16(x), l = fp16(x - h). Two values packed per reg.
__device__ __forceinline__ void split_h2(float x0, float x1, uint32_t& h, uint32_t& l)
{
    __half h0 = __float2half_rn(x0);
    __half h1 = __float2half_rn(x1);
    float r0 = x0 - __half2float(h0);
    float r1 = x1 - __half2float(h1);
    __half l0 = __float2half_rn(r0);
    __half l1 = __float2half_rn(r1);
    h = ((uint32_t)__half_as_ushort(h1) << 16) | (uint32_t)__half_as_ushort(h0);
    l = ((uint32_t)__half_as_ushort(l1) << 16) | (uint32_t)__half_as_ushort(l0);
}

__device__ __forceinline__ void mma_f16(float* c, const uint32_t* a, const uint32_t* b)
{
    asm volatile(
        "mma.sync.aligned.m16n8k16.row.col.f32.f16.f16.f32 "
        "{%0,%1,%2,%3}, {%4,%5,%6,%7}, {%8,%9}, {%0,%1,%2,%3};\n"
        : "+f"(c[0]), "+f"(c[1]), "+f"(c[2]), "+f"(c[3])
        : "r"(a[0]), "r"(a[1]), "r"(a[2]), "r"(a[3]),
          "r"(b[0]), "r"(b[1]));
}

// ---------------- FP16x3 tensor-core gather-GEMM (BK=32) -------------------
// out[M,Cout] = sum_{k in [k0,k1)} X[nbr[m,k]] @ W[k]  (nbr==null -> identity)
// Block tile 64 x TBN, 256 threads (8 warps, 4M x 2N). fp32 staged in smem;
// fp16 hi/lo split in registers at fragment-load; 3 m16n8k16 mma per 16-deep
// K (al*bh + ah*bl + ah*bh) for ~22-bit effective precision.
template<int TBN>
__global__ __launch_bounds__(256)
void gmma_t(const float* __restrict__ X,
            const int*   __restrict__ nbr,
            const float* __restrict__ W,
            const float* __restrict__ bias,
            float* __restrict__ out,
            int M, int Cin, int Cout, int Koff, int k0, int k1, int doRelu)
{
    constexpr int TBM = 64;
    constexpr int BKC = 32;                 // K-chunk per stage
    constexpr int PA  = BKC + 4;            // A pitch ([m][k] layout)
    constexpr int PB  = TBN + 8;            // B pitch ([k][n] layout)
    constexpr int NF  = TBN / 16;           // n-frags per warp
    constexpr int BV  = (8 * TBN + 255) / 256;   // B float4 tasks / thread

    extern __shared__ float sm[];
    float* As = sm;                           // [2][TBM][PA]  fp32
    float* Bs = As + 2 * TBM * PA;            // [2][BKC][PB]  fp32
    int*   rows = (int*)(Bs + 2 * BKC * PB);  // [nk][TBM], nk <= 27

    const int tid  = threadIdx.x;
    const int m0   = blockIdx.y * TBM;
    const int n0   = blockIdx.x * TBN;
    const int warp = tid >> 5, lane = tid & 31;
    const int wm = warp >> 1, wn = warp & 1;
    const int lg = lane >> 2, lt = lane & 3;

    const int nk      = k1 - k0;
    const int kchunks = (Cin + BKC - 1) / BKC;
    const int nIter   = nk * kchunks;
    const bool bVec = (Cout % 4 == 0) && ((((uintptr_t)W) & 15u) == 0u)
                      && (((Cin * Cout) & 3) == 0);

    for (int idx = tid; idx < nk * TBM; idx += 256) {
        int kk = idx / TBM, mi = idx - kk * TBM;
        int m  = m0 + mi;
        rows[kk * TBM + mi] = (m < M) ? (nbr ? nbr[(size_t)m * Koff + k0 + kk] : m) : 0;
    }
    __syncthreads();

    float acc[NF][4];
    #pragma unroll
    for (int f = 0; f < NF; ++f)
        #pragma unroll
        for (int j = 0; j < 4; ++j) acc[f][j] = 0.f;

    float4 aR[2];          // A: 512 float4 tasks / 256 threads
    float4 bR[BV];

    auto loadStage = [&](int t) {
        int k   = t / kchunks;
        int cc  = t - k * kchunks;
        int ci0 = cc * BKC;
        #pragma unroll
        for (int v = 0; v < 2; ++v) {
            int task = tid + v * 256;        // < 512
            int mi = task >> 3;
            int cg = (task & 7) << 2;
            int c  = ci0 + cg;
            float4 val = make_float4(0.f, 0.f, 0.f, 0.f);
            if (c < Cin)
                val = *reinterpret_cast<const float4*>(
                          X + (size_t)rows[k * TBM + mi] * Cin + c);
            aR[v] = val;
        }
        const float* Wk = W + (size_t)(k0 + k) * Cin * Cout;
        if (bVec) {
            #pragma unroll
            for (int v = 0; v < BV; ++v) {
                int idx = tid + v * 256;
                float4 val = make_float4(0.f, 0.f, 0.f, 0.f);
                if (idx < 8 * TBN) {
                    int ni = (idx % (TBN / 4)) * 4;
                    int ki = idx / (TBN / 4);
                    int c  = ci0 + ki;
                    int n  = n0 + ni;
                    if (c < Cin && n < Cout)
                        val = *reinterpret_cast<const float4*>(
                                  Wk + (size_t)c * Cout + n);
                }
                bR[v] = val;
            }
        } else {
            #pragma unroll
            for (int v = 0; v < BV; ++v) {
                int idx = tid + v * 256;
                float4 val = make_float4(0.f, 0.f, 0.f, 0.f);
                if (idx < 8 * TBN) {
                    int ni = (idx % (TBN / 4)) * 4;
                    int ki = idx / (TBN / 4);
                    int c  = ci0 + ki;
                    if (c < Cin) {
                        const float* p = Wk + (size_t)c * Cout;
                        int n = n0 + ni;
                        if (n + 0 < Cout) val.x = p[n + 0];
                        if (n + 1 < Cout) val.y = p[n + 1];
                        if (n + 2 < Cout) val.z = p[n + 2];
                        if (n + 3 < Cout) val.w = p[n + 3];
                    }
                }
                bR[v] = val;
            }
        }
    };

    auto storeStage = [&](int s) {
        #pragma unroll
        for (int v = 0; v < 2; ++v) {
            int task = tid + v * 256;
            int mi = task >> 3;
            int cg = (task & 7) << 2;
            *reinterpret_cast<float4*>(As + (s * TBM + mi) * PA + cg) = aR[v];
        }
        #pragma unroll
        for (int v = 0; v < BV; ++v) {
            int idx = tid + v * 256;
            if (idx < 8 * TBN) {
                int ni = (idx % (TBN / 4)) * 4;
                int ki = idx / (TBN / 4);
                *reinterpret_cast<float4*>(Bs + (s * BKC + ki) * PB + ni) = bR[v];
            }
        }
    };

    auto computeStage = [&](int s) {
        #pragma unroll
        for (int ks = 0; ks < 2; ++ks) {
            const int cb = ks * 16;
            const float* aP = As + (s * TBM) * PA;
            const int mA = wm * 16 + lg;
            const int cA = cb + 2 * lt;
            uint32_t ah[4], al[4];
            {
                float2 v0 = *reinterpret_cast<const float2*>(&aP[(mA    ) * PA + cA    ]);
                float2 v1 = *reinterpret_cast<const float2*>(&aP[(mA + 8) * PA + cA    ]);
                float2 v2 = *reinterpret_cast<const float2*>(&aP[(mA    ) * PA + cA + 8]);
                float2 v3 = *reinterpret_cast<const float2*>(&aP[(mA + 8) * PA + cA + 8]);
                split_h2(v0.x, v0.y, ah[0], al[0]);
                split_h2(v1.x, v1.y, ah[1], al[1]);
                split_h2(v2.x, v2.y, ah[2], al[2]);
                split_h2(v3.x, v3.y, ah[3], al[3]);
            }
            const float* bP = Bs + (s * BKC) * PB;
            #pragma unroll
            for (int f = 0; f < NF; ++f) {
                const int nB = wn * (TBN / 2) + f * 8 + lg;
                const int cB = cb + 2 * lt;
                uint32_t bh[2], bl[2];
                split_h2(bP[(cB    ) * PB + nB], bP[(cB + 1) * PB + nB], bh[0], bl[0]);
                split_h2(bP[(cB + 8) * PB + nB], bP[(cB + 9) * PB + nB], bh[1], bl[1]);
                mma_f16(acc[f], al, bh);
                mma_f16(acc[f], ah, bl);
                mma_f16(acc[f], ah, bh);
            }
        }
    };

    loadStage(0);
    storeStage(0);
    __syncthreads();

    for (int t = 0; t < nIter; ++t) {
        int cur = t & 1;
        if (t + 1 < nIter) loadStage(t + 1);
        computeStage(cur);
        if (t + 1 < nIter) storeStage(cur ^ 1);
        __syncthreads();
    }

    // ---- epilogue ----
    #pragma unroll
    for (int f = 0; f < NF; ++f) {
        int nb  = n0 + wn * (TBN / 2) + f * 8;
        int c0i = nb + lt * 2;
        int r   = m0 + wm * 16 + lg;
        float b0v = 0.f, b1v = 0.f;
        if (bias) {
            if (c0i     < Cout) b0v = bias[c0i];
            if (c0i + 1 < Cout) b1v = bias[c0i + 1];
        }
        if (r < M) {
            if (c0i < Cout) {
                float v = acc[f][0] + b0v;
                if (doRelu) v = fmaxf(v, 0.f);
                out[(size_t)r * Cout + c0i] = v;
            }
            if (c0i + 1 < Cout) {
                float v = acc[f][1] + b1v;
                if (doRelu) v = fmaxf(v, 0.f);
                out[(size_t)r * Cout + c0i + 1] = v;
            }
        }
        int r2 = r + 8;
        if (r2 < M) {
            if (c0i < Cout) {
                float v = acc[f][2] + b0v;
                if (doRelu) v = fmaxf(v, 0.f);
                out[(size_t)r2 * Cout + c0i] = v;
            }
            if (c0i + 1 < Cout) {
                float v = acc[f][3] + b1v;
                if (doRelu) v = fmaxf(v, 0.f);
                out[(size_t)r2 * Cout + c0i + 1] = v;
            }
        }
    }
}

// ordered deterministic sum of S split partials
__global__ void reduce_split_kernel(const float* __restrict__ buf,
                                    float* __restrict__ out,
                                    long long MN, int S)
{
    long long i = (long long)blockIdx.x * blockDim.x + threadIdx.x;
    if (i >= MN) return;
    float s = 0.f;
    for (int k = 0; k < S; ++k) s += buf[(size_t)k * MN + i];
    out[i] = s;
}

// ---------------- BN stats (deterministic two-phase) ----------------------
#define STAT_ROWS 256
__global__ void bn_stats_kernel(const float* __restrict__ x, int M, int C,
                                float* __restrict__ p1, float* __restrict__ p2)
{
    const int r0   = blockIdx.x * STAT_ROWS;
    const int rend = min(r0 + STAT_ROWS, M);
    const int c0 = threadIdx.x;
    const int c1 = threadIdx.x + 256;
    float a0 = 0.f, q0 = 0.f, a1 = 0.f, q1 = 0.f;
    for (int r = r0; r < rend; ++r) {
        const float* row = x + (size_t)r * C;
        if (c0 < C) { float v = row[c0]; a0 += v; q0 += v * v; }
        if (c1 < C) { float v = row[c1]; a1 += v; q1 += v * v; }
    }
    float* o1 = p1 + (size_t)blockIdx.x * 512;
    float* o2 = p2 + (size_t)blockIdx.x * 512;
    if (c0 < C) { o1[c0] = a0; o2[c0] = q0; }
    if (c1 < C) { o1[c1] = a1; o2[c1] = q1; }
}

__global__ void bn_finalize_kernel(const float* __restrict__ p1,
                                   const float* __restrict__ p2,
                                   int nblk, int M, int C,
                                   float* __restrict__ mean,
                                   float* __restrict__ istd)
{
    int warp = (blockIdx.x * blockDim.x + threadIdx.x) >> 5;
    int lane = threadIdx.x & 31;
    if (warp >= C) return;
    float s1 = 0.f, s2 = 0.f;
    for (int b = lane; b < nblk; b += 32) {
        s1 += p1[(size_t)b * 512 + warp];
        s2 += p2[(size_t)b * 512 + warp];
    }
    #pragma unroll
    for (int o = 16; o > 0; o >>= 1) {
        s1 += __shfl_down_sync(0xffffffffu, s1, o);
        s2 += __shfl_down_sync(0xffffffffu, s2, o);
    }
    if (lane == 0) {
        float m = s1 / (float)M;
        float v = s2 / (float)M - m * m;
        mean[warp] = m;
        istd[warp] = rsqrtf(v + 1e-5f);
    }
}

// mode 0: relu((a-m0)*i0); 1: relu(bn(a)+b); 2: relu(bn(a)+bn2(b))
__global__ void bn_apply_kernel(const float* __restrict__ a,
                                const float* __restrict__ b,
                                const float* __restrict__ m0, const float* __restrict__ i0,
                                const float* __restrict__ m1, const float* __restrict__ i1,
                                float* __restrict__ out, int M, int C, int mode)
{
    size_t i = (size_t)blockIdx.x * blockDim.x + threadIdx.x;
    size_t total = (size_t)M * C;
    if (i >= total) return;
    int c = (int)(i % (size_t)C);
    float v = (a[i] - m0[c]) * i0[c];
    if (mode == 1)      v += b[i];
    else if (mode == 2) v += (b[i] - m1[c]) * i1[c];
    out[i] = fmaxf(v, 0.f);
}

// ---------------- transposed conv ----------------------------------------
__global__ void deconv_kernel(const float* __restrict__ X,
                              const int* __restrict__ parent,
                              const int* __restrict__ koff,
                              const float* __restrict__ W,
                              float* __restrict__ out,
                              int M, int Cin, int Cout)
{
    __shared__ float xs[256];
    const int m = blockIdx.x;
    const int p = parent[m];
    const int o = koff[m];
    for (int c = threadIdx.x; c < Cin; c += blockDim.x)
        xs[c] = X[(size_t)p * Cin + c];
    __syncthreads();
    const float* Wk = W + (size_t)o * Cin * Cout;
    for (int n = threadIdx.x; n < Cout; n += blockDim.x) {
        float acc = 0.f;
        #pragma unroll 4
        for (int ci = 0; ci < Cin; ++ci)
            acc += xs[ci] * Wk[(size_t)ci * Cout + n];
        out[(size_t)m * Cout + n] = acc;
    }
}

__global__ void concat_kernel(const float* __restrict__ a, const float* __restrict__ b,
                              float* __restrict__ out, int M, int Ca, int Cb)
{
    size_t i = (size_t)blockIdx.x * blockDim.x + threadIdx.x;
    const int C = Ca + Cb;
    size_t total = (size_t)M * C;
    if (i >= total) return;
    int r = (int)(i / (size_t)C);
    int c = (int)(i % (size_t)C);
    out[i] = (c < Ca) ? a[(size_t)r * Ca + c] : b[(size_t)r * Cb + (c - Ca)];
}

// ---------------- host-side orchestration --------------------------------
static float *TA, *TB, *Y, *X0, *X1, *X2, *X3, *X4, *SPL, *P1, *P2, *MEAN, *ISTD;
static const float* gP;
static size_t gOff;

static inline const float* takeP(size_t n) { const float* w = gP + gOff; gOff += n; return w; }
static inline int cdiv(int a, int b) { return (a + b - 1) / b; }

static inline size_t gmma_smem(int TBN)
{
    int PB = TBN + 8;
    size_t floats = (size_t)2 * 64 * 36 + (size_t)2 * 32 * PB + 27 * 64;
    return floats * 4;
}

static void launch_gmma(int TBN, dim3 grid,
                        const float* X, const int* nbr, const float* W,
                        const float* bias, float* out,
                        int M, int Cin, int Cout, int K, int k0, int k1, int relu)
{
    size_t sh = gmma_smem(TBN);
    switch (TBN) {
    case 32: gmma_t<32><<<grid, 256, sh>>>(X, nbr, W, bias, out, M, Cin, Cout, K, k0, k1, relu); break;
    case 96: gmma_t<96><<<grid, 256, sh>>>(X, nbr, W, bias, out, M, Cin, Cout, K, k0, k1, relu); break;
    default: gmma_t<64><<<grid, 256, sh>>>(X, nbr, W, bias, out, M, Cin, Cout, K, k0, k1, relu); break;
    }
}

static void run_conv(const float* X, const int* nbr, const float* W, float* out,
                     int M, int Cin, int Cout, int K,
                     const float* bias = nullptr, int relu = 0)
{
    int TBN = (Cout == 96) ? 96 : (Cout <= 32 ? 32 : 64);
    dim3 grid(cdiv(Cout, TBN), cdiv(M, 64));
    int blocks = grid.x * grid.y;

    int S = 1, kper = K;
    if (nbr && K > 1 && blocks < 296) {
        S = (296 + blocks - 1) / blocks;
        if (S > K) S = K;
        kper = (K + S - 1) / S;
        S = (K + kper - 1) / kper;
    }
    if (S == 1) {
        launch_gmma(TBN, grid, X, nbr, W, bias, out, M, Cin, Cout, K, 0, K, relu);
    } else {
        long long MN = (long long)M * Cout;
        for (int s = 0; s < S; ++s) {
            int k0 = s * kper;
            int k1 = k0 + kper; if (k1 > K) k1 = K;
            launch_gmma(TBN, grid, X, nbr, W, nullptr, SPL + (size_t)s * MN,
                        M, Cin, Cout, K, k0, k1, 0);
        }
        reduce_split_kernel<<<(unsigned)((MN + 255) / 256), 256>>>(SPL, out, MN, S);
    }
}

static void run_bn(const float* a, int M, int C, int slot)
{
    int nb = cdiv(M, STAT_ROWS);
    bn_stats_kernel<<<nb, 256>>>(a, M, C, P1, P2);
    bn_finalize_kernel<<<cdiv(C * 32, 256), 256>>>(P1, P2, nb, M, C,
                                                   MEAN + slot * 512, ISTD + slot * 512);
}

static void run_apply(const float* a, const float* b, float* out, int M, int C, int mode)
{
    size_t total = (size_t)M * C;
    bn_apply_kernel<<<(unsigned)((total + 255) / 256), 256>>>(
        a, b, MEAN, ISTD, MEAN + 512, ISTD + 512, out, M, C, mode);
}

static void cbr(const float* x, const int* nbr, int M, int Cin, int Cout, int K, float* out)
{
    const float* w = takeP((size_t)K * Cin * Cout);
    run_conv(x, nbr, w, TA, M, Cin, Cout, K);
    run_bn(TA, M, Cout, 0);
    run_apply(TA, nullptr, out, M, Cout, 0);
}

static void resblock(const float* x, const int* nbr, int M, int ci, int co, float* out)
{
    const float* w1 = takeP((size_t)27 * ci * co);
    const float* w2 = takeP((size_t)27 * co * co);
    run_conv(x, nbr, w1, TA, M, ci, co, 27);
    run_bn(TA, M, co, 0);
    run_apply(TA, nullptr, TB, M, co, 0);
    run_conv(TB, nbr, w2, TA, M, co, co, 27);
    run_bn(TA, M, co, 0);
    if (ci != co) {
        const float* ws = takeP((size_t)ci * co);
        run_conv(x, nullptr, ws, TB, M, ci, co, 1);
        run_bn(TB, M, co, 1);
        run_apply(TA, TB, out, M, co, 2);
    } else {
        run_apply(TA, x, out, M, co, 1);
    }
}

static void up_block(const float* x, const int* par, const int* off, int M,
                     int Cin, int Cout, const float* skip, int Cskip, float* out)
{
    const float* w = takeP((size_t)8 * Cin * Cout);
    deconv_kernel<<<M, 128>>>(x, par, off, w, TA, M, Cin, Cout);
    run_bn(TA, M, Cout, 0);
    run_apply(TA, nullptr, TB, M, Cout, 0);
    size_t total = (size_t)M * (Cout + Cskip);
    concat_kernel<<<(unsigned)((total + 255) / 256), 256>>>(TB, skip, out, M, Cout, Cskip);
}

extern "C" void kernel_launch(void* const* d_in, const int* in_sizes, int n_in,
                              void* d_out, int out_size)
{
    const float* x    = (const float*)d_in[0];
    const int* nbr0   = (const int*)d_in[1];
    const int* nbr1   = (const int*)d_in[2];
    const int* nbr2   = (const int*)d_in[3];
    const int* nbr3   = (const int*)d_in[4];
    const int* nbr4   = (const int*)d_in[5];
    const int* d1     = (const int*)d_in[6];
    const int* d2     = (const int*)d_in[7];
    const int* d3     = (const int*)d_in[8];
    const int* d4     = (const int*)d_in[9];
    const int* u1p    = (const int*)d_in[10];
    const int* u1o    = (const int*)d_in[11];
    const int* u2p    = (const int*)d_in[12];
    const int* u2o    = (const int*)d_in[13];
    const int* u3p    = (const int*)d_in[14];
    const int* u3o    = (const int*)d_in[15];
    const int* u4p    = (const int*)d_in[16];
    const int* u4o    = (const int*)d_in[17];
    gP = (const float*)d_in[18];
    gOff = 0;

    // allow >48KB dynamic smem (needed for TBN=96; harmless otherwise)
    cudaFuncSetAttribute((const void*)gmma_t<32>,
                         cudaFuncAttributeMaxDynamicSharedMemorySize, 65536);
    cudaFuncSetAttribute((const void*)gmma_t<64>,
                         cudaFuncAttributeMaxDynamicSharedMemorySize, 65536);
    cudaFuncSetAttribute((const void*)gmma_t<96>,
                         cudaFuncAttributeMaxDynamicSharedMemorySize, 65536);

    cudaGetSymbolAddress((void**)&X0,   g_x0);
    cudaGetSymbolAddress((void**)&X1,   g_x1);
    cudaGetSymbolAddress((void**)&X2,   g_x2);
    cudaGetSymbolAddress((void**)&X3,   g_x3);
    cudaGetSymbolAddress((void**)&X4,   g_x4);
    cudaGetSymbolAddress((void**)&Y,    g_y);
    cudaGetSymbolAddress((void**)&TA,   g_ta);
    cudaGetSymbolAddress((void**)&TB,   g_tb);
    cudaGetSymbolAddress((void**)&SPL,  g_split);
    cudaGetSymbolAddress((void**)&P1,   g_p1);
    cudaGetSymbolAddress((void**)&P2,   g_p2);
    cudaGetSymbolAddress((void**)&MEAN, g_mean);
    cudaGetSymbolAddress((void**)&ISTD, g_istd);

    // ---- stem (N0) ----
    cbr(x,  nbr0, NN0, 4,  32, 27, X0);
    cbr(X0, nbr0, NN0, 32, 32, 27, X0);

    // ---- stage1 (N1) ----
    cbr(X0, d1, NN1, 32, 32, 8, Y);
    resblock(Y, nbr1, NN1, 32, 32, Y);
    resblock(Y, nbr1, NN1, 32, 32, X1);

    // ---- stage2 (N2) ----
    cbr(X1, d2, NN2, 32, 32, 8, Y);
    resblock(Y, nbr2, NN2, 32, 64, Y);
    resblock(Y, nbr2, NN2, 64, 64, X2);

    // ---- stage3 (N3) ----
    cbr(X2, d3, NN3, 64, 64, 8, Y);
    resblock(Y, nbr3, NN3, 64, 128, Y);
    resblock(Y, nbr3, NN3, 128, 128, X3);

    // ---- stage4 (N4) ----
    cbr(X3, d4, NN4, 128, 128, 8, Y);
    resblock(Y, nbr4, NN4, 128, 256, Y);
    resblock(Y, nbr4, NN4, 256, 256, X4);

    // ---- up1 (N3) ----
    up_block(X4, u1p, u1o, NN3, 256, 256, X3, 128, Y);
    resblock(Y, nbr3, NN3, 384, 256, Y);
    resblock(Y, nbr3, NN3, 256, 256, Y);

    // ---- up2 (N2) ----
    up_block(Y, u2p, u2o, NN2, 256, 128, X2, 64, Y);
    resblock(Y, nbr2, NN2, 192, 128, Y);
    resblock(Y, nbr2, NN2, 128, 128, Y);

    // ---- up3 (N1) ----
    up_block(Y, u3p, u3o, NN1, 128, 96, X1, 32, Y);
    resblock(Y, nbr1, NN1, 128, 96, Y);
    resblock(Y, nbr1, NN1, 96, 96, Y);

    // ---- up4 (N0) ----
    up_block(Y, u4p, u4o, NN0, 96, 96, X0, 32, Y);
    resblock(Y, nbr0, NN0, 128, 96, Y);
    resblock(Y, nbr0, NN0, 96, 96, Y);

    // ---- head ----
    const float* wc = takeP((size_t)96 * 19);
    const float* bc = takeP(19);
    const float* w1 = takeP((size_t)96 * 96);
    const float* b1 = takeP(96);
    const float* w2 = takeP((size_t)96 * 128);
    const float* b2 = takeP(128);

    float* out = (float*)d_out;
    run_conv(Y, nullptr, wc, out, NN0, 96, 19, 1, bc, 0);
    run_conv(Y,  nullptr, w1, TA, NN0, 96, 96, 1, b1, 1);
    run_conv(TA, nullptr, w2, out + (size_t)NN0 * 19, NN0, 96, 128, 1, b2, 0);
}

// round 15
// speedup vs baseline: 1.5707x; 1.5707x over previous
#include <cuda_runtime.h>
#include <cuda_fp16.h>
#include <cstddef>
#include <cstdint>

#define NN0 50000
#define NN1 20000
#define NN2 8000
#define NN3 3200
#define NN4 1300

// ---------------- device scratch (no allocation allowed) ----------------
__device__ float g_x0[NN0 * 32];
__device__ float g_x1[NN1 * 32];
__device__ float g_x2[NN2 * 64];
__device__ float g_x3[NN3 * 128];
__device__ float g_x4[NN4 * 256];
__device__ float g_y [NN0 * 128];
__device__ float g_ta[NN0 * 128];
__device__ float g_tb[NN0 * 128];
__device__ float g_split[4 * 1024 * 1024];
__device__ float g_p1[800 * 512];
__device__ float g_p2[800 * 512];
__device__ float g_mean[2 * 512];
__device__ float g_istd[2 * 512];

// ---------------- fp16 hi/lo helpers --------------------------------------
// packs (x0,x1) -> h2 = (fp16(x1)<<16)|fp16(x0), l2 = residuals likewise
__device__ __forceinline__ void split2(float x0, float x1, uint32_t& h, uint32_t& l)
{
    __half2 hh = __floats2half2_rn(x0, x1);
    float r0 = x0 - __low2float(hh);
    float r1 = x1 - __high2float(hh);
    __half2 ll = __floats2half2_rn(r0, r1);
    h = *reinterpret_cast<uint32_t*>(&hh);
    l = *reinterpret_cast<uint32_t*>(&ll);
}

__device__ __forceinline__ void mma_f16(float* c, const uint32_t* a, const uint32_t* b)
{
    asm volatile(
        "mma.sync.aligned.m16n8k16.row.col.f32.f16.f16.f32 "
        "{%0,%1,%2,%3}, {%4,%5,%6,%7}, {%8,%9}, {%0,%1,%2,%3};\n"
        : "+f"(c[0]), "+f"(c[1]), "+f"(c[2]), "+f"(c[3])
        : "r"(a[0]), "r"(a[1]), "r"(a[2]), "r"(a[3]),
          "r"(b[0]), "r"(b[1]));
}

// ---------------- FP16x3 tensor-core gather-GEMM (BK=32, smem pre-split) ---
// out[M,Cout] = sum_{k in [k0,k1)} X[nbr[m,k]] @ W[k]  (nbr==null -> identity)
// 64 x TBN tile, 256 threads (8 warps, 4M x 2N). Hi/lo fp16 split done ONCE
// per element at smem-store; fragments read packed half2 directly.
// A smem: half [TBM][PAh] (H and L). B smem: uint32(half2 k-pair) [16][PBn].
template<int TBN>
__global__ __launch_bounds__(256)
void gmma_t(const float* __restrict__ X,
            const int*   __restrict__ nbr,
            const float* __restrict__ W,
            const float* __restrict__ bias,
            float* __restrict__ out,
            int M, int Cin, int Cout, int Koff, int k0, int k1, int doRelu)
{
    constexpr int TBM = 64;
    constexpr int BKC = 32;                 // K-chunk per stage
    constexpr int PAh = BKC + 8;            // A pitch in halves (40: 8 mod 32 shift)
    constexpr int PBn = TBN + 8;            // B pitch in half2 units
    constexpr int NF  = TBN / 16;           // n-frags per warp
    constexpr int BT  = 4 * TBN;            // B k-pair tasks (each: 2 float4 loads)
    constexpr int BV  = (BT + 255) / 256;

    extern __shared__ char smB[];
    __half*   AsH = reinterpret_cast<__half*>(smB);                 // [2][TBM][PAh]
    __half*   AsL = AsH + 2 * TBM * PAh;
    uint32_t* BsH = reinterpret_cast<uint32_t*>(AsL + 2 * TBM * PAh); // [2][16][PBn]
    uint32_t* BsL = BsH + 2 * 16 * PBn;
    int*      rows = reinterpret_cast<int*>(BsL + 2 * 16 * PBn);    // [nk][TBM]

    const int tid  = threadIdx.x;
    const int m0   = blockIdx.y * TBM;
    const int n0   = blockIdx.x * TBN;
    const int warp = tid >> 5, lane = tid & 31;
    const int wm = warp >> 1, wn = warp & 1;
    const int lg = lane >> 2, lt = lane & 3;

    const int nk      = k1 - k0;
    const int kchunks = (Cin + BKC - 1) / BKC;
    const int nIter   = nk * kchunks;
    const bool bVec = (Cout % 4 == 0) && ((((uintptr_t)W) & 15u) == 0u)
                      && (((Cin * Cout) & 3) == 0);

    for (int idx = tid; idx < nk * TBM; idx += 256) {
        int kk = idx / TBM, mi = idx - kk * TBM;
        int m  = m0 + mi;
        rows[kk * TBM + mi] = (m < M) ? (nbr ? nbr[(size_t)m * Koff + k0 + kk] : m) : 0;
    }
    __syncthreads();

    float acc[NF][4];
    #pragma unroll
    for (int f = 0; f < NF; ++f)
        #pragma unroll
        for (int j = 0; j < 4; ++j) acc[f][j] = 0.f;

    float4 aR[2];              // A: 512 float4 tasks / 256 threads
    float4 bR0[BV], bR1[BV];   // B: per task two k-rows (even, odd)

    auto loadStage = [&](int t) {
        int k   = t / kchunks;
        int cc  = t - k * kchunks;
        int ci0 = cc * BKC;
        #pragma unroll
        for (int v = 0; v < 2; ++v) {
            int task = tid + v * 256;        // < 512
            int mi = task >> 3;
            int cg = (task & 7) << 2;
            int c  = ci0 + cg;
            float4 val = make_float4(0.f, 0.f, 0.f, 0.f);
            if (c < Cin)
                val = *reinterpret_cast<const float4*>(
                          X + (size_t)rows[k * TBM + mi] * Cin + c);
            aR[v] = val;
        }
        const float* Wk = W + (size_t)(k0 + k) * Cin * Cout;
        #pragma unroll
        for (int v = 0; v < BV; ++v) {
            int task = tid + v * 256;
            float4 v0 = make_float4(0.f, 0.f, 0.f, 0.f);
            float4 v1 = v0;
            if (task < BT) {
                int kp = task / (TBN / 4);
                int ni = (task % (TBN / 4)) * 4;
                int c0 = ci0 + 2 * kp;
                int n  = n0 + ni;
                if (bVec) {
                    if (c0 < Cin && n < Cout) {
                        v0 = *reinterpret_cast<const float4*>(Wk + (size_t)c0 * Cout + n);
                        if (c0 + 1 < Cin)
                            v1 = *reinterpret_cast<const float4*>(Wk + (size_t)(c0 + 1) * Cout + n);
                    }
                } else {
                    if (c0 < Cin) {
                        const float* p = Wk + (size_t)c0 * Cout;
                        if (n + 0 < Cout) v0.x = p[n + 0];
                        if (n + 1 < Cout) v0.y = p[n + 1];
                        if (n + 2 < Cout) v0.z = p[n + 2];
                        if (n + 3 < Cout) v0.w = p[n + 3];
                    }
                    if (c0 + 1 < Cin) {
                        const float* p = Wk + (size_t)(c0 + 1) * Cout;
                        if (n + 0 < Cout) v1.x = p[n + 0];
                        if (n + 1 < Cout) v1.y = p[n + 1];
                        if (n + 2 < Cout) v1.z = p[n + 2];
                        if (n + 3 < Cout) v1.w = p[n + 3];
                    }
                }
            }
            bR0[v] = v0;
            bR1[v] = v1;
        }
    };

    auto storeStage = [&](int s) {
        #pragma unroll
        for (int v = 0; v < 2; ++v) {
            int task = tid + v * 256;
            int mi = task >> 3;
            int cg = (task & 7) << 2;
            uint32_t h0, l0, h1, l1;
            split2(aR[v].x, aR[v].y, h0, l0);
            split2(aR[v].z, aR[v].w, h1, l1);
            int off = (s * TBM + mi) * PAh + cg;      // half index, 8B aligned
            *reinterpret_cast<uint2*>(AsH + off) = make_uint2(h0, h1);
            *reinterpret_cast<uint2*>(AsL + off) = make_uint2(l0, l1);
        }
        #pragma unroll
        for (int v = 0; v < BV; ++v) {
            int task = tid + v * 256;
            if (task < BT) {
                int kp = task / (TBN / 4);
                int ni = (task % (TBN / 4)) * 4;
                uint32_t h[4], l[4];
                split2(bR0[v].x, bR1[v].x, h[0], l[0]);
                split2(bR0[v].y, bR1[v].y, h[1], l[1]);
                split2(bR0[v].z, bR1[v].z, h[2], l[2]);
                split2(bR0[v].w, bR1[v].w, h[3], l[3]);
                int off = (s * 16 + kp) * PBn + ni;   // u32 index, 16B aligned
                *reinterpret_cast<uint4*>(BsH + off) = make_uint4(h[0], h[1], h[2], h[3]);
                *reinterpret_cast<uint4*>(BsL + off) = make_uint4(l[0], l[1], l[2], l[3]);
            }
        }
    };

    auto computeStage = [&](int s) {
        #pragma unroll
        for (int ks = 0; ks < 2; ++ks) {
            const int cb = ks * 16;
            const __half* aH = AsH + (s * TBM) * PAh;
            const __half* aL = AsL + (s * TBM) * PAh;
            const int mA = wm * 16 + lg;
            const int cA = cb + 2 * lt;
            uint32_t ah[4], al[4];
            ah[0] = *reinterpret_cast<const uint32_t*>(aH + (mA    ) * PAh + cA    );
            ah[1] = *reinterpret_cast<const uint32_t*>(aH + (mA + 8) * PAh + cA    );
            ah[2] = *reinterpret_cast<const uint32_t*>(aH + (mA    ) * PAh + cA + 8);
            ah[3] = *reinterpret_cast<const uint32_t*>(aH + (mA + 8) * PAh + cA + 8);
            al[0] = *reinterpret_cast<const uint32_t*>(aL + (mA    ) * PAh + cA    );
            al[1] = *reinterpret_cast<const uint32_t*>(aL + (mA + 8) * PAh + cA    );
            al[2] = *reinterpret_cast<const uint32_t*>(aL + (mA    ) * PAh + cA + 8);
            al[3] = *reinterpret_cast<const uint32_t*>(aL + (mA + 8) * PAh + cA + 8);
            const uint32_t* bHp = BsH + (s * 16 + ks * 8) * PBn;
            const uint32_t* bLp = BsL + (s * 16 + ks * 8) * PBn;
            #pragma unroll
            for (int f = 0; f < NF; ++f) {
                const int nB = wn * (TBN / 2) + f * 8 + lg;
                uint32_t bh[2], bl[2];
                bh[0] = bHp[(lt    ) * PBn + nB];
                bh[1] = bHp[(lt + 4) * PBn + nB];
                bl[0] = bLp[(lt    ) * PBn + nB];
                bl[1] = bLp[(lt + 4) * PBn + nB];
                mma_f16(acc[f], al, bh);
                mma_f16(acc[f], ah, bl);
                mma_f16(acc[f], ah, bh);
            }
        }
    };

    loadStage(0);
    storeStage(0);
    __syncthreads();

    for (int t = 0; t < nIter; ++t) {
        int cur = t & 1;
        if (t + 1 < nIter) loadStage(t + 1);
        computeStage(cur);
        if (t + 1 < nIter) storeStage(cur ^ 1);
        __syncthreads();
    }

    // ---- epilogue ----
    #pragma unroll
    for (int f = 0; f < NF; ++f) {
        int nb  = n0 + wn * (TBN / 2) + f * 8;
        int c0i = nb + lt * 2;
        int r   = m0 + wm * 16 + lg;
        float b0v = 0.f, b1v = 0.f;
        if (bias) {
            if (c0i     < Cout) b0v = bias[c0i];
            if (c0i + 1 < Cout) b1v = bias[c0i + 1];
        }
        if (r < M) {
            if (c0i < Cout) {
                float v = acc[f][0] + b0v;
                if (doRelu) v = fmaxf(v, 0.f);
                out[(size_t)r * Cout + c0i] = v;
            }
            if (c0i + 1 < Cout) {
                float v = acc[f][1] + b1v;
                if (doRelu) v = fmaxf(v, 0.f);
                out[(size_t)r * Cout + c0i + 1] = v;
            }
        }
        int r2 = r + 8;
        if (r2 < M) {
            if (c0i < Cout) {
                float v = acc[f][2] + b0v;
                if (doRelu) v = fmaxf(v, 0.f);
                out[(size_t)r2 * Cout + c0i] = v;
            }
            if (c0i + 1 < Cout) {
                float v = acc[f][3] + b1v;
                if (doRelu) v = fmaxf(v, 0.f);
                out[(size_t)r2 * Cout + c0i + 1] = v;
            }
        }
    }
}

// ordered deterministic sum of S split partials
__global__ void reduce_split_kernel(const float* __restrict__ buf,
                                    float* __restrict__ out,
                                    long long MN, int S)
{
    long long i = (long long)blockIdx.x * blockDim.x + threadIdx.x;
    if (i >= MN) return;
    float s = 0.f;
    for (int k = 0; k < S; ++k) s += buf[(size_t)k * MN + i];
    out[i] = s;
}

// ---------------- BN stats (deterministic two-phase) ----------------------
#define STAT_ROWS 256
__global__ void bn_stats_kernel(const float* __restrict__ x, int M, int C,
                                float* __restrict__ p1, float* __restrict__ p2)
{
    const int r0   = blockIdx.x * STAT_ROWS;
    const int rend = min(r0 + STAT_ROWS, M);
    const int c0 = threadIdx.x;
    const int c1 = threadIdx.x + 256;
    float a0 = 0.f, q0 = 0.f, a1 = 0.f, q1 = 0.f;
    for (int r = r0; r < rend; ++r) {
        const float* row = x + (size_t)r * C;
        if (c0 < C) { float v = row[c0]; a0 += v; q0 += v * v; }
        if (c1 < C) { float v = row[c1]; a1 += v; q1 += v * v; }
    }
    float* o1 = p1 + (size_t)blockIdx.x * 512;
    float* o2 = p2 + (size_t)blockIdx.x * 512;
    if (c0 < C) { o1[c0] = a0; o2[c0] = q0; }
    if (c1 < C) { o1[c1] = a1; o2[c1] = q1; }
}

__global__ void bn_finalize_kernel(const float* __restrict__ p1,
                                   const float* __restrict__ p2,
                                   int nblk, int M, int C,
                                   float* __restrict__ mean,
                                   float* __restrict__ istd)
{
    int warp = (blockIdx.x * blockDim.x + threadIdx.x) >> 5;
    int lane = threadIdx.x & 31;
    if (warp >= C) return;
    float s1 = 0.f, s2 = 0.f;
    for (int b = lane; b < nblk; b += 32) {
        s1 += p1[(size_t)b * 512 + warp];
        s2 += p2[(size_t)b * 512 + warp];
    }
    #pragma unroll
    for (int o = 16; o > 0; o >>= 1) {
        s1 += __shfl_down_sync(0xffffffffu, s1, o);
        s2 += __shfl_down_sync(0xffffffffu, s2, o);
    }
    if (lane == 0) {
        float m = s1 / (float)M;
        float v = s2 / (float)M - m * m;
        mean[warp] = m;
        istd[warp] = rsqrtf(v + 1e-5f);
    }
}

// mode 0: relu((a-m0)*i0); 1: relu(bn(a)+b); 2: relu(bn(a)+bn2(b))
__global__ void bn_apply_kernel(const float* __restrict__ a,
                                const float* __restrict__ b,
                                const float* __restrict__ m0, const float* __restrict__ i0,
                                const float* __restrict__ m1, const float* __restrict__ i1,
                                float* __restrict__ out, int M, int C, int mode)
{
    size_t i = (size_t)blockIdx.x * blockDim.x + threadIdx.x;
    size_t total = (size_t)M * C;
    if (i >= total) return;
    int c = (int)(i % (size_t)C);
    float v = (a[i] - m0[c]) * i0[c];
    if (mode == 1)      v += b[i];
    else if (mode == 2) v += (b[i] - m1[c]) * i1[c];
    out[i] = fmaxf(v, 0.f);
}

// ---------------- transposed conv ----------------------------------------
__global__ void deconv_kernel(const float* __restrict__ X,
                              const int* __restrict__ parent,
                              const int* __restrict__ koff,
                              const float* __restrict__ W,
                              float* __restrict__ out,
                              int M, int Cin, int Cout)
{
    __shared__ float xs[256];
    const int m = blockIdx.x;
    const int p = parent[m];
    const int o = koff[m];
    for (int c = threadIdx.x; c < Cin; c += blockDim.x)
        xs[c] = X[(size_t)p * Cin + c];
    __syncthreads();
    const float* Wk = W + (size_t)o * Cin * Cout;
    for (int n = threadIdx.x; n < Cout; n += blockDim.x) {
        float acc = 0.f;
        #pragma unroll 4
        for (int ci = 0; ci < Cin; ++ci)
            acc += xs[ci] * Wk[(size_t)ci * Cout + n];
        out[(size_t)m * Cout + n] = acc;
    }
}

__global__ void concat_kernel(const float* __restrict__ a, const float* __restrict__ b,
                              float* __restrict__ out, int M, int Ca, int Cb)
{
    size_t i = (size_t)blockIdx.x * blockDim.x + threadIdx.x;
    const int C = Ca + Cb;
    size_t total = (size_t)M * C;
    if (i >= total) return;
    int r = (int)(i / (size_t)C);
    int c = (int)(i % (size_t)C);
    out[i] = (c < Ca) ? a[(size_t)r * Ca + c] : b[(size_t)r * Cb + (c - Ca)];
}

// ---------------- host-side orchestration --------------------------------
static float *TA, *TB, *Y, *X0, *X1, *X2, *X3, *X4, *SPL, *P1, *P2, *MEAN, *ISTD;
static const float* gP;
static size_t gOff;

static inline const float* takeP(size_t n) { const float* w = gP + gOff; gOff += n; return w; }
static inline int cdiv(int a, int b) { return (a + b - 1) / b; }

static inline size_t gmma_smem(int TBN)
{
    int PBn = TBN + 8;
    size_t bytes = (size_t)2 * 64 * 40 * 2 * 2      // AsH + AsL (halves)
                 + (size_t)2 * 16 * PBn * 4 * 2     // BsH + BsL (u32)
                 + (size_t)27 * 64 * 4;             // rows
    return bytes;
}

static void launch_gmma(int TBN, dim3 grid,
                        const float* X, const int* nbr, const float* W,
                        const float* bias, float* out,
                        int M, int Cin, int Cout, int K, int k0, int k1, int relu)
{
    size_t sh = gmma_smem(TBN);
    switch (TBN) {
    case 32: gmma_t<32><<<grid, 256, sh>>>(X, nbr, W, bias, out, M, Cin, Cout, K, k0, k1, relu); break;
    case 96: gmma_t<96><<<grid, 256, sh>>>(X, nbr, W, bias, out, M, Cin, Cout, K, k0, k1, relu); break;
    default: gmma_t<64><<<grid, 256, sh>>>(X, nbr, W, bias, out, M, Cin, Cout, K, k0, k1, relu); break;
    }
}

static void run_conv(const float* X, const int* nbr, const float* W, float* out,
                     int M, int Cin, int Cout, int K,
                     const float* bias = nullptr, int relu = 0)
{
    int TBN = (Cout == 96) ? 96 : (Cout <= 32 ? 32 : 64);
    dim3 grid(cdiv(Cout, TBN), cdiv(M, 64));
    int blocks = grid.x * grid.y;

    int S = 1, kper = K;
    if (nbr && K > 1 && blocks < 296) {
        S = (296 + blocks - 1) / blocks;
        if (S > K) S = K;
        kper = (K + S - 1) / S;
        S = (K + kper - 1) / kper;
    }
    if (S == 1) {
        launch_gmma(TBN, grid, X, nbr, W, bias, out, M, Cin, Cout, K, 0, K, relu);
    } else {
        long long MN = (long long)M * Cout;
        for (int s = 0; s < S; ++s) {
            int k0 = s * kper;
            int k1 = k0 + kper; if (k1 > K) k1 = K;
            launch_gmma(TBN, grid, X, nbr, W, nullptr, SPL + (size_t)s * MN,
                        M, Cin, Cout, K, k0, k1, 0);
        }
        reduce_split_kernel<<<(unsigned)((MN + 255) / 256), 256>>>(SPL, out, MN, S);
    }
}

static void run_bn(const float* a, int M, int C, int slot)
{
    int nb = cdiv(M, STAT_ROWS);
    bn_stats_kernel<<<nb, 256>>>(a, M, C, P1, P2);
    bn_finalize_kernel<<<cdiv(C * 32, 256), 256>>>(P1, P2, nb, M, C,
                                                   MEAN + slot * 512, ISTD + slot * 512);
}

static void run_apply(const float* a, const float* b, float* out, int M, int C, int mode)
{
    size_t total = (size_t)M * C;
    bn_apply_kernel<<<(unsigned)((total + 255) / 256), 256>>>(
        a, b, MEAN, ISTD, MEAN + 512, ISTD + 512, out, M, C, mode);
}

static void cbr(const float* x, const int* nbr, int M, int Cin, int Cout, int K, float* out)
{
    const float* w = takeP((size_t)K * Cin * Cout);
    run_conv(x, nbr, w, TA, M, Cin, Cout, K);
    run_bn(TA, M, Cout, 0);
    run_apply(TA, nullptr, out, M, Cout, 0);
}

static void resblock(const float* x, const int* nbr, int M, int ci, int co, float* out)
{
    const float* w1 = takeP((size_t)27 * ci * co);
    const float* w2 = takeP((size_t)27 * co * co);
    run_conv(x, nbr, w1, TA, M, ci, co, 27);
    run_bn(TA, M, co, 0);
    run_apply(TA, nullptr, TB, M, co, 0);
    run_conv(TB, nbr, w2, TA, M, co, co, 27);
    run_bn(TA, M, co, 0);
    if (ci != co) {
        const float* ws = takeP((size_t)ci * co);
        run_conv(x, nullptr, ws, TB, M, ci, co, 1);
        run_bn(TB, M, co, 1);
        run_apply(TA, TB, out, M, co, 2);
    } else {
        run_apply(TA, x, out, M, co, 1);
    }
}

static void up_block(const float* x, const int* par, const int* off, int M,
                     int Cin, int Cout, const float* skip, int Cskip, float* out)
{
    const float* w = takeP((size_t)8 * Cin * Cout);
    deconv_kernel<<<M, 128>>>(x, par, off, w, TA, M, Cin, Cout);
    run_bn(TA, M, Cout, 0);
    run_apply(TA, nullptr, TB, M, Cout, 0);
    size_t total = (size_t)M * (Cout + Cskip);
    concat_kernel<<<(unsigned)((total + 255) / 256), 256>>>(TB, skip, out, M, Cout, Cskip);
}

extern "C" void kernel_launch(void* const* d_in, const int* in_sizes, int n_in,
                              void* d_out, int out_size)
{
    const float* x    = (const float*)d_in[0];
    const int* nbr0   = (const int*)d_in[1];
    const int* nbr1   = (const int*)d_in[2];
    const int* nbr2   = (const int*)d_in[3];
    const int* nbr3   = (const int*)d_in[4];
    const int* nbr4   = (const int*)d_in[5];
    const int* d1     = (const int*)d_in[6];
    const int* d2     = (const int*)d_in[7];
    const int* d3     = (const int*)d_in[8];
    const int* d4     = (const int*)d_in[9];
    const int* u1p    = (const int*)d_in[10];
    const int* u1o    = (const int*)d_in[11];
    const int* u2p    = (const int*)d_in[12];
    const int* u2o    = (const int*)d_in[13];
    const int* u3p    = (const int*)d_in[14];
    const int* u3o    = (const int*)d_in[15];
    const int* u4p    = (const int*)d_in[16];
    const int* u4o    = (const int*)d_in[17];
    gP = (const float*)d_in[18];
    gOff = 0;

    // allow >48KB dynamic smem (TBN=96 needs ~54KB)
    cudaFuncSetAttribute((const void*)gmma_t<32>,
                         cudaFuncAttributeMaxDynamicSharedMemorySize, 65536);
    cudaFuncSetAttribute((const void*)gmma_t<64>,
                         cudaFuncAttributeMaxDynamicSharedMemorySize, 65536);
    cudaFuncSetAttribute((const void*)gmma_t<96>,
                         cudaFuncAttributeMaxDynamicSharedMemorySize, 65536);

    cudaGetSymbolAddress((void**)&X0,   g_x0);
    cudaGetSymbolAddress((void**)&X1,   g_x1);
    cudaGetSymbolAddress((void**)&X2,   g_x2);
    cudaGetSymbolAddress((void**)&X3,   g_x3);
    cudaGetSymbolAddress((void**)&X4,   g_x4);
    cudaGetSymbolAddress((void**)&Y,    g_y);
    cudaGetSymbolAddress((void**)&TA,   g_ta);
    cudaGetSymbolAddress((void**)&TB,   g_tb);
    cudaGetSymbolAddress((void**)&SPL,  g_split);
    cudaGetSymbolAddress((void**)&P1,   g_p1);
    cudaGetSymbolAddress((void**)&P2,   g_p2);
    cudaGetSymbolAddress((void**)&MEAN, g_mean);
    cudaGetSymbolAddress((void**)&ISTD, g_istd);

    // ---- stem (N0) ----
    cbr(x,  nbr0, NN0, 4,  32, 27, X0);
    cbr(X0, nbr0, NN0, 32, 32, 27, X0);

    // ---- stage1 (N1) ----
    cbr(X0, d1, NN1, 32, 32, 8, Y);
    resblock(Y, nbr1, NN1, 32, 32, Y);
    resblock(Y, nbr1, NN1, 32, 32, X1);

    // ---- stage2 (N2) ----
    cbr(X1, d2, NN2, 32, 32, 8, Y);
    resblock(Y, nbr2, NN2, 32, 64, Y);
    resblock(Y, nbr2, NN2, 64, 64, X2);

    // ---- stage3 (N3) ----
    cbr(X2, d3, NN3, 64, 64, 8, Y);
    resblock(Y, nbr3, NN3, 64, 128, Y);
    resblock(Y, nbr3, NN3, 128, 128, X3);

    // ---- stage4 (N4) ----
    cbr(X3, d4, NN4, 128, 128, 8, Y);
    resblock(Y, nbr4, NN4, 128, 256, Y);
    resblock(Y, nbr4, NN4, 256, 256, X4);

    // ---- up1 (N3) ----
    up_block(X4, u1p, u1o, NN3, 256, 256, X3, 128, Y);
    resblock(Y, nbr3, NN3, 384, 256, Y);
    resblock(Y, nbr3, NN3, 256, 256, Y);

    // ---- up2 (N2) ----
    up_block(Y, u2p, u2o, NN2, 256, 128, X2, 64, Y);
    resblock(Y, nbr2, NN2, 192, 128, Y);
    resblock(Y, nbr2, NN2, 128, 128, Y);

    // ---- up3 (N1) ----
    up_block(Y, u3p, u3o, NN1, 128, 96, X1, 32, Y);
    resblock(Y, nbr1, NN1, 128, 96, Y);
    resblock(Y, nbr1, NN1, 96, 96, Y);

    // ---- up4 (N0) ----
    up_block(Y, u4p, u4o, NN0, 96, 96, X0, 32, Y);
    resblock(Y, nbr0, NN0, 128, 96, Y);
    resblock(Y, nbr0, NN0, 96, 96, Y);

    // ---- head ----
    const float* wc = takeP((size_t)96 * 19);
    const float* bc = takeP(19);
    const float* w1 = takeP((size_t)96 * 96);
    const float* b1 = takeP(96);
    const float* w2 = takeP((size_t)96 * 128);
    const float* b2 = takeP(128);

    float* out = (float*)d_out;
    run_conv(Y, nullptr, wc, out, NN0, 96, 19, 1, bc, 0);
    run_conv(Y,  nullptr, w1, TA, NN0, 96, 96, 1, b1, 1);
    run_conv(TA, nullptr, w2, out + (size_t)NN0 * 19, NN0, 96, 128, 1, b2, 0);
}

// round 16
// speedup vs baseline: 1.5848x; 1.0090x over previous
#include <cuda_runtime.h>
#include <cuda_fp16.h>
#include <cstddef>
#include <cstdint>

#define NN0 50000
#define NN1 20000
#define NN2 8000
#define NN3 3200
#define NN4 1300

// ---------------- device scratch (no allocation allowed) ----------------
__device__ float g_x0[NN0 * 32];
__device__ float g_x1[NN1 * 32];
__device__ float g_x2[NN2 * 64];
__device__ float g_x3[NN3 * 128];
__device__ float g_x4[NN4 * 256];
__device__ float g_y [NN0 * 128];
__device__ float g_ta[NN0 * 128];
__device__ float g_tb[NN0 * 128];
__device__ float g_split[4 * 1024 * 1024];
__device__ float g_p1[800 * 512];
__device__ float g_p2[800 * 512];
__device__ float g_mean[2 * 512];
__device__ float g_istd[2 * 512];

// ---------------- fp16 hi/lo helpers --------------------------------------
__device__ __forceinline__ void split2(float x0, float x1, uint32_t& h, uint32_t& l)
{
    __half2 hh = __floats2half2_rn(x0, x1);
    float r0 = x0 - __low2float(hh);
    float r1 = x1 - __high2float(hh);
    __half2 ll = __floats2half2_rn(r0, r1);
    h = *reinterpret_cast<uint32_t*>(&hh);
    l = *reinterpret_cast<uint32_t*>(&ll);
}

__device__ __forceinline__ void mma_f16(float* c, const uint32_t* a, const uint32_t* b)
{
    asm volatile(
        "mma.sync.aligned.m16n8k16.row.col.f32.f16.f16.f32 "
        "{%0,%1,%2,%3}, {%4,%5,%6,%7}, {%8,%9}, {%0,%1,%2,%3};\n"
        : "+f"(c[0]), "+f"(c[1]), "+f"(c[2]), "+f"(c[3])
        : "r"(a[0]), "r"(a[1]), "r"(a[2]), "r"(a[3]),
          "r"(b[0]), "r"(b[1]));
}

// ---------------- FP16x3 tensor-core gather-GEMM (BK=32, smem pre-split) ---
// out[M,Cout] = sum_{k in [k0,k1)} X[nbr[m,k]] @ W[k]  (nbr==null -> identity)
// 256 threads. TBM=64: 8 warps as 4Mx2N. TBM=128: 8 warps as 8Mx1N.
// Hi/lo fp16 split done ONCE per element at smem-store.
template<int TBM, int TBN>
__global__ __launch_bounds__(256)
void gmma_t(const float* __restrict__ X,
            const int*   __restrict__ nbr,
            const float* __restrict__ W,
            const float* __restrict__ bias,
            float* __restrict__ out,
            int M, int Cin, int Cout, int Koff, int k0, int k1, int doRelu)
{
    constexpr int BKC = 32;
    constexpr int PAh = BKC + 8;            // A pitch in halves (40)
    constexpr int PBn = TBN + 8;            // B pitch in half2 units
    constexpr int WN  = (TBM >= 128) ? 1 : 2;
    constexpr int NF  = TBN / (8 * WN);     // n-frags per warp
    constexpr int AV  = TBM / 32;           // A float4 tasks / thread
    constexpr int BT  = 4 * TBN;            // B k-pair tasks
    constexpr int BV  = (BT + 255) / 256;

    extern __shared__ char smB[];
    __half*   AsH = reinterpret_cast<__half*>(smB);                   // [2][TBM][PAh]
    __half*   AsL = AsH + 2 * TBM * PAh;
    uint32_t* BsH = reinterpret_cast<uint32_t*>(AsL + 2 * TBM * PAh); // [2][16][PBn]
    uint32_t* BsL = BsH + 2 * 16 * PBn;
    int*      rows = reinterpret_cast<int*>(BsL + 2 * 16 * PBn);      // [nk][TBM]

    const int tid  = threadIdx.x;
    const int m0   = blockIdx.y * TBM;
    const int n0   = blockIdx.x * TBN;
    const int warp = tid >> 5, lane = tid & 31;
    const int wm = warp / WN, wn = warp % WN;
    const int lg = lane >> 2, lt = lane & 3;

    const int nk      = k1 - k0;
    const int kchunks = (Cin + BKC - 1) / BKC;
    const int nIter   = nk * kchunks;
    const bool bVec = (Cout % 4 == 0) && ((((uintptr_t)W) & 15u) == 0u)
                      && (((Cin * Cout) & 3) == 0);

    for (int idx = tid; idx < nk * TBM; idx += 256) {
        int kk = idx / TBM, mi = idx - kk * TBM;
        int m  = m0 + mi;
        rows[kk * TBM + mi] = (m < M) ? (nbr ? nbr[(size_t)m * Koff + k0 + kk] : m) : 0;
    }
    __syncthreads();

    float acc[NF][4];
    #pragma unroll
    for (int f = 0; f < NF; ++f)
        #pragma unroll
        for (int j = 0; j < 4; ++j) acc[f][j] = 0.f;

    float4 aR[AV];
    float4 bR0[BV], bR1[BV];

    auto loadStage = [&](int t) {
        int k   = t / kchunks;
        int cc  = t - k * kchunks;
        int ci0 = cc * BKC;
        #pragma unroll
        for (int v = 0; v < AV; ++v) {
            int task = tid + v * 256;        // < TBM*8
            int mi = task >> 3;
            int cg = (task & 7) << 2;
            int c  = ci0 + cg;
            float4 val = make_float4(0.f, 0.f, 0.f, 0.f);
            if (c < Cin)
                val = *reinterpret_cast<const float4*>(
                          X + (size_t)rows[k * TBM + mi] * Cin + c);
            aR[v] = val;
        }
        const float* Wk = W + (size_t)(k0 + k) * Cin * Cout;
        #pragma unroll
        for (int v = 0; v < BV; ++v) {
            int task = tid + v * 256;
            float4 v0 = make_float4(0.f, 0.f, 0.f, 0.f);
            float4 v1 = v0;
            if (task < BT) {
                int kp = task / (TBN / 4);
                int ni = (task % (TBN / 4)) * 4;
                int c0 = ci0 + 2 * kp;
                int n  = n0 + ni;
                if (bVec) {
                    if (c0 < Cin && n < Cout) {
                        v0 = *reinterpret_cast<const float4*>(Wk + (size_t)c0 * Cout + n);
                        if (c0 + 1 < Cin)
                            v1 = *reinterpret_cast<const float4*>(Wk + (size_t)(c0 + 1) * Cout + n);
                    }
                } else {
                    if (c0 < Cin) {
                        const float* p = Wk + (size_t)c0 * Cout;
                        if (n + 0 < Cout) v0.x = p[n + 0];
                        if (n + 1 < Cout) v0.y = p[n + 1];
                        if (n + 2 < Cout) v0.z = p[n + 2];
                        if (n + 3 < Cout) v0.w = p[n + 3];
                    }
                    if (c0 + 1 < Cin) {
                        const float* p = Wk + (size_t)(c0 + 1) * Cout;
                        if (n + 0 < Cout) v1.x = p[n + 0];
                        if (n + 1 < Cout) v1.y = p[n + 1];
                        if (n + 2 < Cout) v1.z = p[n + 2];
                        if (n + 3 < Cout) v1.w = p[n + 3];
                    }
                }
            }
            bR0[v] = v0;
            bR1[v] = v1;
        }
    };

    auto storeStage = [&](int s) {
        #pragma unroll
        for (int v = 0; v < AV; ++v) {
            int task = tid + v * 256;
            int mi = task >> 3;
            int cg = (task & 7) << 2;
            uint32_t h0, l0, h1, l1;
            split2(aR[v].x, aR[v].y, h0, l0);
            split2(aR[v].z, aR[v].w, h1, l1);
            int off = (s * TBM + mi) * PAh + cg;
            *reinterpret_cast<uint2*>(AsH + off) = make_uint2(h0, h1);
            *reinterpret_cast<uint2*>(AsL + off) = make_uint2(l0, l1);
        }
        #pragma unroll
        for (int v = 0; v < BV; ++v) {
            int task = tid + v * 256;
            if (task < BT) {
                int kp = task / (TBN / 4);
                int ni = (task % (TBN / 4)) * 4;
                uint32_t h[4], l[4];
                split2(bR0[v].x, bR1[v].x, h[0], l[0]);
                split2(bR0[v].y, bR1[v].y, h[1], l[1]);
                split2(bR0[v].z, bR1[v].z, h[2], l[2]);
                split2(bR0[v].w, bR1[v].w, h[3], l[3]);
                int off = (s * 16 + kp) * PBn + ni;
                *reinterpret_cast<uint4*>(BsH + off) = make_uint4(h[0], h[1], h[2], h[3]);
                *reinterpret_cast<uint4*>(BsL + off) = make_uint4(l[0], l[1], l[2], l[3]);
            }
        }
    };

    auto computeStage = [&](int s) {
        #pragma unroll
        for (int ks = 0; ks < 2; ++ks) {
            const int cb = ks * 16;
            const __half* aH = AsH + (s * TBM) * PAh;
            const __half* aL = AsL + (s * TBM) * PAh;
            const int mA = wm * 16 + lg;
            const int cA = cb + 2 * lt;
            uint32_t ah[4], al[4];
            ah[0] = *reinterpret_cast<const uint32_t*>(aH + (mA    ) * PAh + cA    );
            ah[1] = *reinterpret_cast<const uint32_t*>(aH + (mA + 8) * PAh + cA    );
            ah[2] = *reinterpret_cast<const uint32_t*>(aH + (mA    ) * PAh + cA + 8);
            ah[3] = *reinterpret_cast<const uint32_t*>(aH + (mA + 8) * PAh + cA + 8);
            al[0] = *reinterpret_cast<const uint32_t*>(aL + (mA    ) * PAh + cA    );
            al[1] = *reinterpret_cast<const uint32_t*>(aL + (mA + 8) * PAh + cA    );
            al[2] = *reinterpret_cast<const uint32_t*>(aL + (mA    ) * PAh + cA + 8);
            al[3] = *reinterpret_cast<const uint32_t*>(aL + (mA + 8) * PAh + cA + 8);
            const uint32_t* bHp = BsH + (s * 16 + ks * 8) * PBn;
            const uint32_t* bLp = BsL + (s * 16 + ks * 8) * PBn;
            #pragma unroll
            for (int f = 0; f < NF; ++f) {
                const int nB = wn * (TBN / WN) + f * 8 + lg;
                uint32_t bh[2], bl[2];
                bh[0] = bHp[(lt    ) * PBn + nB];
                bh[1] = bHp[(lt + 4) * PBn + nB];
                bl[0] = bLp[(lt    ) * PBn + nB];
                bl[1] = bLp[(lt + 4) * PBn + nB];
                mma_f16(acc[f], al, bh);
                mma_f16(acc[f], ah, bl);
                mma_f16(acc[f], ah, bh);
            }
        }
    };

    loadStage(0);
    storeStage(0);
    __syncthreads();

    for (int t = 0; t < nIter; ++t) {
        int cur = t & 1;
        if (t + 1 < nIter) loadStage(t + 1);
        computeStage(cur);
        if (t + 1 < nIter) storeStage(cur ^ 1);
        __syncthreads();
    }

    // ---- epilogue ----
    #pragma unroll
    for (int f = 0; f < NF; ++f) {
        int nb  = n0 + wn * (TBN / WN) + f * 8;
        int c0i = nb + lt * 2;
        int r   = m0 + wm * 16 + lg;
        float b0v = 0.f, b1v = 0.f;
        if (bias) {
            if (c0i     < Cout) b0v = bias[c0i];
            if (c0i + 1 < Cout) b1v = bias[c0i + 1];
        }
        if (r < M) {
            if (c0i < Cout) {
                float v = acc[f][0] + b0v;
                if (doRelu) v = fmaxf(v, 0.f);
                out[(size_t)r * Cout + c0i] = v;
            }
            if (c0i + 1 < Cout) {
                float v = acc[f][1] + b1v;
                if (doRelu) v = fmaxf(v, 0.f);
                out[(size_t)r * Cout + c0i + 1] = v;
            }
        }
        int r2 = r + 8;
        if (r2 < M) {
            if (c0i < Cout) {
                float v = acc[f][2] + b0v;
                if (doRelu) v = fmaxf(v, 0.f);
                out[(size_t)r2 * Cout + c0i] = v;
            }
            if (c0i + 1 < Cout) {
                float v = acc[f][3] + b1v;
                if (doRelu) v = fmaxf(v, 0.f);
                out[(size_t)r2 * Cout + c0i + 1] = v;
            }
        }
    }
}

// ordered deterministic sum of S split partials
__global__ void reduce_split_kernel(const float* __restrict__ buf,
                                    float* __restrict__ out,
                                    long long MN, int S)
{
    long long i = (long long)blockIdx.x * blockDim.x + threadIdx.x;
    if (i >= MN) return;
    float s = 0.f;
    for (int k = 0; k < S; ++k) s += buf[(size_t)k * MN + i];
    out[i] = s;
}

// ---------------- BN stats (deterministic two-phase) ----------------------
#define STAT_ROWS 256
__global__ void bn_stats_kernel(const float* __restrict__ x, int M, int C,
                                float* __restrict__ p1, float* __restrict__ p2)
{
    const int r0   = blockIdx.x * STAT_ROWS;
    const int rend = min(r0 + STAT_ROWS, M);
    const int c0 = threadIdx.x;
    const int c1 = threadIdx.x + 256;
    float a0 = 0.f, q0 = 0.f, a1 = 0.f, q1 = 0.f;
    for (int r = r0; r < rend; ++r) {
        const float* row = x + (size_t)r * C;
        if (c0 < C) { float v = row[c0]; a0 += v; q0 += v * v; }
        if (c1 < C) { float v = row[c1]; a1 += v; q1 += v * v; }
    }
    float* o1 = p1 + (size_t)blockIdx.x * 512;
    float* o2 = p2 + (size_t)blockIdx.x * 512;
    if (c0 < C) { o1[c0] = a0; o2[c0] = q0; }
    if (c1 < C) { o1[c1] = a1; o2[c1] = q1; }
}

__global__ void bn_finalize_kernel(const float* __restrict__ p1,
                                   const float* __restrict__ p2,
                                   int nblk, int M, int C,
                                   float* __restrict__ mean,
                                   float* __restrict__ istd)
{
    int warp = (blockIdx.x * blockDim.x + threadIdx.x) >> 5;
    int lane = threadIdx.x & 31;
    if (warp >= C) return;
    float s1 = 0.f, s2 = 0.f;
    for (int b = lane; b < nblk; b += 32) {
        s1 += p1[(size_t)b * 512 + warp];
        s2 += p2[(size_t)b * 512 + warp];
    }
    #pragma unroll
    for (int o = 16; o > 0; o >>= 1) {
        s1 += __shfl_down_sync(0xffffffffu, s1, o);
        s2 += __shfl_down_sync(0xffffffffu, s2, o);
    }
    if (lane == 0) {
        float m = s1 / (float)M;
        float v = s2 / (float)M - m * m;
        mean[warp] = m;
        istd[warp] = rsqrtf(v + 1e-5f);
    }
}

// float4-vectorized BN apply (C % 4 == 0 always in this net)
// mode 0: relu(bn(a)); 1: relu(bn(a)+b); 2: relu(bn(a)+bn2(b))
__global__ void bn_apply_kernel(const float* __restrict__ a,
                                const float* __restrict__ b,
                                const float* __restrict__ m0, const float* __restrict__ i0,
                                const float* __restrict__ m1, const float* __restrict__ i1,
                                float* __restrict__ out, int M, int C, int mode)
{
    size_t i = (size_t)blockIdx.x * blockDim.x + threadIdx.x;
    int C4 = C >> 2;
    size_t total4 = (size_t)M * C4;
    if (i >= total4) return;
    int c = (int)(i % (size_t)C4) << 2;
    float4 va = reinterpret_cast<const float4*>(a)[i];
    float4 r;
    r.x = (va.x - m0[c + 0]) * i0[c + 0];
    r.y = (va.y - m0[c + 1]) * i0[c + 1];
    r.z = (va.z - m0[c + 2]) * i0[c + 2];
    r.w = (va.w - m0[c + 3]) * i0[c + 3];
    if (mode == 1) {
        float4 vb = reinterpret_cast<const float4*>(b)[i];
        r.x += vb.x; r.y += vb.y; r.z += vb.z; r.w += vb.w;
    } else if (mode == 2) {
        float4 vb = reinterpret_cast<const float4*>(b)[i];
        r.x += (vb.x - m1[c + 0]) * i1[c + 0];
        r.y += (vb.y - m1[c + 1]) * i1[c + 1];
        r.z += (vb.z - m1[c + 2]) * i1[c + 2];
        r.w += (vb.w - m1[c + 3]) * i1[c + 3];
    }
    r.x = fmaxf(r.x, 0.f); r.y = fmaxf(r.y, 0.f);
    r.z = fmaxf(r.z, 0.f); r.w = fmaxf(r.w, 0.f);
    reinterpret_cast<float4*>(out)[i] = r;
}

// ---------------- transposed conv ----------------------------------------
__global__ void deconv_kernel(const float* __restrict__ X,
                              const int* __restrict__ parent,
                              const int* __restrict__ koff,
                              const float* __restrict__ W,
                              float* __restrict__ out,
                              int M, int Cin, int Cout)
{
    __shared__ float xs[256];
    const int m = blockIdx.x;
    const int p = parent[m];
    const int o = koff[m];
    for (int c = threadIdx.x; c < Cin; c += blockDim.x)
        xs[c] = X[(size_t)p * Cin + c];
    __syncthreads();
    const float* Wk = W + (size_t)o * Cin * Cout;
    for (int n = threadIdx.x; n < Cout; n += blockDim.x) {
        float acc = 0.f;
        #pragma unroll 4
        for (int ci = 0; ci < Cin; ++ci)
            acc += xs[ci] * Wk[(size_t)ci * Cout + n];
        out[(size_t)m * Cout + n] = acc;
    }
}

// float4-vectorized concat (Ca, Cb % 4 == 0 always)
__global__ void concat_kernel(const float* __restrict__ a, const float* __restrict__ b,
                              float* __restrict__ out, int M, int Ca, int Cb)
{
    size_t i = (size_t)blockIdx.x * blockDim.x + threadIdx.x;
    int C4 = (Ca + Cb) >> 2;
    size_t total4 = (size_t)M * C4;
    if (i >= total4) return;
    int r  = (int)(i / (size_t)C4);
    int c4 = (int)(i % (size_t)C4) << 2;
    float4 v;
    if (c4 < Ca)
        v = reinterpret_cast<const float4*>(a + (size_t)r * Ca)[c4 >> 2];
    else
        v = reinterpret_cast<const float4*>(b + (size_t)r * Cb)[(c4 - Ca) >> 2];
    reinterpret_cast<float4*>(out + (size_t)r * (Ca + Cb))[c4 >> 2] = v;
}

// ---------------- host-side orchestration --------------------------------
static float *TA, *TB, *Y, *X0, *X1, *X2, *X3, *X4, *SPL, *P1, *P2, *MEAN, *ISTD;
static const float* gP;
static size_t gOff;

static inline const float* takeP(size_t n) { const float* w = gP + gOff; gOff += n; return w; }
static inline int cdiv(int a, int b) { return (a + b - 1) / b; }

static inline size_t gmma_smem(int TBM, int TBN)
{
    int PBn = TBN + 8;
    size_t bytes = (size_t)2 * TBM * 40 * 2 * 2      // AsH + AsL (halves)
                 + (size_t)2 * 16 * PBn * 4 * 2      // BsH + BsL (u32)
                 + (size_t)27 * TBM * 4;             // rows
    return bytes;
}

static void launch_gmma(int TBM, int TBN, dim3 grid,
                        const float* X, const int* nbr, const float* W,
                        const float* bias, float* out,
                        int M, int Cin, int Cout, int K, int k0, int k1, int relu)
{
    size_t sh = gmma_smem(TBM, TBN);
    if (TBM == 128) {
        switch (TBN) {
        case 32: gmma_t<128, 32><<<grid, 256, sh>>>(X, nbr, W, bias, out, M, Cin, Cout, K, k0, k1, relu); break;
        case 48: gmma_t<128, 48><<<grid, 256, sh>>>(X, nbr, W, bias, out, M, Cin, Cout, K, k0, k1, relu); break;
        default: gmma_t<128, 64><<<grid, 256, sh>>>(X, nbr, W, bias, out, M, Cin, Cout, K, k0, k1, relu); break;
        }
    } else {
        switch (TBN) {
        case 32: gmma_t<64, 32><<<grid, 256, sh>>>(X, nbr, W, bias, out, M, Cin, Cout, K, k0, k1, relu); break;
        case 96: gmma_t<64, 96><<<grid, 256, sh>>>(X, nbr, W, bias, out, M, Cin, Cout, K, k0, k1, relu); break;
        default: gmma_t<64, 64><<<grid, 256, sh>>>(X, nbr, W, bias, out, M, Cin, Cout, K, k0, k1, relu); break;
        }
    }
}

static void run_conv(const float* X, const int* nbr, const float* W, float* out,
                     int M, int Cin, int Cout, int K,
                     const float* bias = nullptr, int relu = 0)
{
    int TBM, TBN;
    if (Cout == 96) {
        if ((long long)cdiv(M, 128) * 2 >= 148) { TBM = 128; TBN = 48; }
        else                                    { TBM = 64;  TBN = 96; }
    } else if (Cout <= 32) {
        if (cdiv(M, 128) >= 148) { TBM = 128; TBN = 32; }
        else                     { TBM = 64;  TBN = 32; }
    } else {
        if ((long long)cdiv(M, 128) * cdiv(Cout, 64) >= 148) { TBM = 128; TBN = 64; }
        else                                                 { TBM = 64;  TBN = 64; }
    }
    dim3 grid(cdiv(Cout, TBN), cdiv(M, TBM));
    int blocks = grid.x * grid.y;

    int S = 1, kper = K;
    if (nbr && K > 1 && blocks < 296 && TBM == 64) {
        S = (296 + blocks - 1) / blocks;
        if (S > K) S = K;
        kper = (K + S - 1) / S;
        S = (K + kper - 1) / kper;
    }
    if (S == 1) {
        launch_gmma(TBM, TBN, grid, X, nbr, W, bias, out, M, Cin, Cout, K, 0, K, relu);
    } else {
        long long MN = (long long)M * Cout;
        for (int s = 0; s < S; ++s) {
            int k0 = s * kper;
            int k1 = k0 + kper; if (k1 > K) k1 = K;
            launch_gmma(TBM, TBN, grid, X, nbr, W, nullptr, SPL + (size_t)s * MN,
                        M, Cin, Cout, K, k0, k1, 0);
        }
        reduce_split_kernel<<<(unsigned)((MN + 255) / 256), 256>>>(SPL, out, MN, S);
    }
}

static void run_bn(const float* a, int M, int C, int slot)
{
    int nb = cdiv(M, STAT_ROWS);
    bn_stats_kernel<<<nb, 256>>>(a, M, C, P1, P2);
    bn_finalize_kernel<<<cdiv(C * 32, 256), 256>>>(P1, P2, nb, M, C,
                                                   MEAN + slot * 512, ISTD + slot * 512);
}

static void run_apply(const float* a, const float* b, float* out, int M, int C, int mode)
{
    size_t total4 = (size_t)M * (C >> 2);
    bn_apply_kernel<<<(unsigned)((total4 + 255) / 256), 256>>>(
        a, b, MEAN, ISTD, MEAN + 512, ISTD + 512, out, M, C, mode);
}

static void cbr(const float* x, const int* nbr, int M, int Cin, int Cout, int K, float* out)
{
    const float* w = takeP((size_t)K * Cin * Cout);
    run_conv(x, nbr, w, TA, M, Cin, Cout, K);
    run_bn(TA, M, Cout, 0);
    run_apply(TA, nullptr, out, M, Cout, 0);
}

static void resblock(const float* x, const int* nbr, int M, int ci, int co, float* out)
{
    const float* w1 = takeP((size_t)27 * ci * co);
    const float* w2 = takeP((size_t)27 * co * co);
    run_conv(x, nbr, w1, TA, M, ci, co, 27);
    run_bn(TA, M, co, 0);
    run_apply(TA, nullptr, TB, M, co, 0);
    run_conv(TB, nbr, w2, TA, M, co, co, 27);
    run_bn(TA, M, co, 0);
    if (ci != co) {
        const float* ws = takeP((size_t)ci * co);
        run_conv(x, nullptr, ws, TB, M, ci, co, 1);
        run_bn(TB, M, co, 1);
        run_apply(TA, TB, out, M, co, 2);
    } else {
        run_apply(TA, x, out, M, co, 1);
    }
}

static void up_block(const float* x, const int* par, const int* off, int M,
                     int Cin, int Cout, const float* skip, int Cskip, float* out)
{
    const float* w = takeP((size_t)8 * Cin * Cout);
    deconv_kernel<<<M, 128>>>(x, par, off, w, TA, M, Cin, Cout);
    run_bn(TA, M, Cout, 0);
    run_apply(TA, nullptr, TB, M, Cout, 0);
    size_t total4 = (size_t)M * ((Cout + Cskip) >> 2);
    concat_kernel<<<(unsigned)((total4 + 255) / 256), 256>>>(TB, skip, out, M, Cout, Cskip);
}

extern "C" void kernel_launch(void* const* d_in, const int* in_sizes, int n_in,
                              void* d_out, int out_size)
{
    const float* x    = (const float*)d_in[0];
    const int* nbr0   = (const int*)d_in[1];
    const int* nbr1   = (const int*)d_in[2];
    const int* nbr2   = (const int*)d_in[3];
    const int* nbr3   = (const int*)d_in[4];
    const int* nbr4   = (const int*)d_in[5];
    const int* d1     = (const int*)d_in[6];
    const int* d2     = (const int*)d_in[7];
    const int* d3     = (const int*)d_in[8];
    const int* d4     = (const int*)d_in[9];
    const int* u1p    = (const int*)d_in[10];
    const int* u1o    = (const int*)d_in[11];
    const int* u2p    = (const int*)d_in[12];
    const int* u2o    = (const int*)d_in[13];
    const int* u3p    = (const int*)d_in[14];
    const int* u3o    = (const int*)d_in[15];
    const int* u4p    = (const int*)d_in[16];
    const int* u4o    = (const int*)d_in[17];
    gP = (const float*)d_in[18];
    gOff = 0;

    // opt-in smem above 48KB for the large-tile variants
    cudaFuncSetAttribute((const void*)gmma_t< 64, 32>, cudaFuncAttributeMaxDynamicSharedMemorySize, 101376);
    cudaFuncSetAttribute((const void*)gmma_t< 64, 64>, cudaFuncAttributeMaxDynamicSharedMemorySize, 101376);
    cudaFuncSetAttribute((const void*)gmma_t< 64, 96>, cudaFuncAttributeMaxDynamicSharedMemorySize, 101376);
    cudaFuncSetAttribute((const void*)gmma_t<128, 32>, cudaFuncAttributeMaxDynamicSharedMemorySize, 101376);
    cudaFuncSetAttribute((const void*)gmma_t<128, 48>, cudaFuncAttributeMaxDynamicSharedMemorySize, 101376);
    cudaFuncSetAttribute((const void*)gmma_t<128, 64>, cudaFuncAttributeMaxDynamicSharedMemorySize, 101376);

    cudaGetSymbolAddress((void**)&X0,   g_x0);
    cudaGetSymbolAddress((void**)&X1,   g_x1);
    cudaGetSymbolAddress((void**)&X2,   g_x2);
    cudaGetSymbolAddress((void**)&X3,   g_x3);
    cudaGetSymbolAddress((void**)&X4,   g_x4);
    cudaGetSymbolAddress((void**)&Y,    g_y);
    cudaGetSymbolAddress((void**)&TA,   g_ta);
    cudaGetSymbolAddress((void**)&TB,   g_tb);
    cudaGetSymbolAddress((void**)&SPL,  g_split);
    cudaGetSymbolAddress((void**)&P1,   g_p1);
    cudaGetSymbolAddress((void**)&P2,   g_p2);
    cudaGetSymbolAddress((void**)&MEAN, g_mean);
    cudaGetSymbolAddress((void**)&ISTD, g_istd);

    // ---- stem (N0) ----
    cbr(x,  nbr0, NN0, 4,  32, 27, X0);
    cbr(X0, nbr0, NN0, 32, 32, 27, X0);

    // ---- stage1 (N1) ----
    cbr(X0, d1, NN1, 32, 32, 8, Y);
    resblock(Y, nbr1, NN1, 32, 32, Y);
    resblock(Y, nbr1, NN1, 32, 32, X1);

    // ---- stage2 (N2) ----
    cbr(X1, d2, NN2, 32, 32, 8, Y);
    resblock(Y, nbr2, NN2, 32, 64, Y);
    resblock(Y, nbr2, NN2, 64, 64, X2);

    // ---- stage3 (N3) ----
    cbr(X2, d3, NN3, 64, 64, 8, Y);
    resblock(Y, nbr3, NN3, 64, 128, Y);
    resblock(Y, nbr3, NN3, 128, 128, X3);

    // ---- stage4 (N4) ----
    cbr(X3, d4, NN4, 128, 128, 8, Y);
    resblock(Y, nbr4, NN4, 128, 256, Y);
    resblock(Y, nbr4, NN4, 256, 256, X4);

    // ---- up1 (N3) ----
    up_block(X4, u1p, u1o, NN3, 256, 256, X3, 128, Y);
    resblock(Y, nbr3, NN3, 384, 256, Y);
    resblock(Y, nbr3, NN3, 256, 256, Y);

    // ---- up2 (N2) ----
    up_block(Y, u2p, u2o, NN2, 256, 128, X2, 64, Y);
    resblock(Y, nbr2, NN2, 192, 128, Y);
    resblock(Y, nbr2, NN2, 128, 128, Y);

    // ---- up3 (N1) ----
    up_block(Y, u3p, u3o, NN1, 128, 96, X1, 32, Y);
    resblock(Y, nbr1, NN1, 128, 96, Y);
    resblock(Y, nbr1, NN1, 96, 96, Y);

    // ---- up4 (N0) ----
    up_block(Y, u4p, u4o, NN0, 96, 96, X0, 32, Y);
    resblock(Y, nbr0, NN0, 128, 96, Y);
    resblock(Y, nbr0, NN0, 96, 96, Y);

    // ---- head ----
    const float* wc = takeP((size_t)96 * 19);
    const float* bc = takeP(19);
    const float* w1 = takeP((size_t)96 * 96);
    const float* b1 = takeP(96);
    const float* w2 = takeP((size_t)96 * 128);
    const float* b2 = takeP(128);

    float* out = (float*)d_out;
    run_conv(Y, nullptr, wc, out, NN0, 96, 19, 1, bc, 0);
    run_conv(Y,  nullptr, w1, TA, NN0, 96, 96, 1, b1, 1);
    run_conv(TA, nullptr, w2, out + (size_t)NN0 * 19, NN0, 96, 128, 1, b2, 0);
}